// round 16
// baseline (speedup 1.0000x reference)
#include <cuda_runtime.h>
#include <cuda_fp16.h>
#include <cstdint>

#define N_NODES 50000
#define N_EDGES 250000
#define D_IN    768
#define D_HID   256

#define M_PAD   50048           // 391 * 128
#define KSTEPS  12              // 768 / 64
#define SCAN_BLOCKS 196         // ceil(50000/256)
#define NCHUNK  4

__device__ __half g_yl[(size_t)N_NODES * 256];  // y_l = x@W1_l^T  (fp16)
__device__ float  g_yr[(size_t)N_NODES * 256];  // y_r = x@W1_r^T  (fp32)
__device__ float  g_z[(size_t)N_NODES * 4];     // zl0,zl1,zr0,zr1
__device__ __half g_A[(size_t)M_PAD * D_IN];    // x fp16; padded rows stay 0
__device__ __half g_B[(size_t)512 * D_IN];      // rows 0..255 = W1_l, 256..511 = W1_r
__device__ int    g_deg[N_NODES];
__device__ int    g_off[N_NODES];
__device__ int    g_pos[N_NODES];
__device__ int    g_srcs[N_EDGES];
__device__ int    g_bsum[SCAN_BLOCKS];
__device__ int    g_bscan[SCAN_BLOCKS];

// ---------------------------------------------------------------------------
// helpers
// ---------------------------------------------------------------------------
__device__ __forceinline__ uint32_t smem_u32(const void* p) {
    uint32_t a;
    asm("{ .reg .u64 t; cvta.to.shared.u64 t, %1; cvt.u32.u64 %0, t; }" : "=r"(a) : "l"(p));
    return a;
}
__device__ __forceinline__ void cp16(uint32_t dst, const void* src) {
    asm volatile("cp.async.cg.shared.global [%0], [%1], 16;" :: "r"(dst), "l"(src));
}
__device__ __forceinline__ void cp_commit() { asm volatile("cp.async.commit_group;" ::: "memory"); }
template <int N> __device__ __forceinline__ void cp_wait() {
    asm volatile("cp.async.wait_group %0;" :: "n"(N) : "memory");
}
__device__ __forceinline__ void ldm_x4(uint32_t* r, uint32_t addr) {
    asm volatile("ldmatrix.sync.aligned.m8n8.x4.shared.b16 {%0,%1,%2,%3}, [%4];"
                 : "=r"(r[0]), "=r"(r[1]), "=r"(r[2]), "=r"(r[3]) : "r"(addr));
}
__device__ __forceinline__ void mma16816(float* d, const uint32_t* a, uint32_t b0, uint32_t b1) {
    asm volatile(
        "mma.sync.aligned.m16n8k16.row.col.f32.f16.f16.f32 "
        "{%0,%1,%2,%3}, {%4,%5,%6,%7}, {%8,%9}, {%0,%1,%2,%3};"
        : "+f"(d[0]), "+f"(d[1]), "+f"(d[2]), "+f"(d[3])
        : "r"(a[0]), "r"(a[1]), "r"(a[2]), "r"(a[3]), "r"(b0), "r"(b1));
}

// ---------------------------------------------------------------------------
// zero degree histogram (side stream, before conv_w's atomics)
// ---------------------------------------------------------------------------
__global__ void zero_deg_kernel() {
    int t = blockIdx.x * 256 + threadIdx.x;
    if (t < N_NODES) g_deg[t] = 0;
}

// ---------------------------------------------------------------------------
// convert x rows [m0, m1) -> fp16 (chunked for pipeline overlap with GEMM)
// ---------------------------------------------------------------------------
__global__ void conv_x_kernel(const float* __restrict__ x, int m0, int m1) {
    int t = blockIdx.x * 256 + threadIdx.x;
    int nrows = m1 - m0;
    if (t >= nrows * (D_IN / 4)) return;
    int m = m0 + t / (D_IN / 4), c4 = t % (D_IN / 4);
    float4 v = *reinterpret_cast<const float4*>(x + (size_t)m * D_IN + c4 * 4);
    __half2 h0 = __floats2half2_rn(v.x, v.y);
    __half2 h1 = __floats2half2_rn(v.z, v.w);
    *reinterpret_cast<uint2*>(g_A + (size_t)m * D_IN + c4 * 4) =
        make_uint2(*reinterpret_cast<uint32_t*>(&h0), *reinterpret_cast<uint32_t*>(&h1));
}

// ---------------------------------------------------------------------------
// convert W1 -> fp16; also histogram dst degrees (after zero_deg on s2)
// ---------------------------------------------------------------------------
__global__ void conv_w_kernel(const float* __restrict__ Wl, const float* __restrict__ Wr,
                              const int* __restrict__ ei) {
    int t = blockIdx.x * 256 + threadIdx.x;
    if (t < N_EDGES) atomicAdd(&g_deg[ei[N_EDGES + t]], 1);
    if (t >= 512 * D_IN) return;
    int r = t / D_IN, c = t % D_IN;
    float v = (r < 256) ? Wl[(size_t)r * D_IN + c] : Wr[(size_t)(r - 256) * D_IN + c];
    g_B[(size_t)r * D_IN + c] = __float2half_rn(v);
}

// ---------------------------------------------------------------------------
// exclusive scan of g_deg -> g_off (3 passes)
// ---------------------------------------------------------------------------
__global__ void scan_a_kernel() {
    __shared__ int s[256];
    int tid = threadIdx.x, t = blockIdx.x * 256 + tid;
    int val = (t < N_NODES) ? g_deg[t] : 0;
    s[tid] = val; __syncthreads();
#pragma unroll
    for (int o = 1; o < 256; o <<= 1) {
        int v = (tid >= o) ? s[tid - o] : 0;
        __syncthreads();
        s[tid] += v;
        __syncthreads();
    }
    if (t < N_NODES) g_off[t] = s[tid] - val;
    if (tid == 255) g_bsum[blockIdx.x] = s[255];
}
__global__ void scan_b_kernel() {
    __shared__ int s[256];
    int tid = threadIdx.x;
    int val = (tid < SCAN_BLOCKS) ? g_bsum[tid] : 0;
    s[tid] = val; __syncthreads();
#pragma unroll
    for (int o = 1; o < 256; o <<= 1) {
        int v = (tid >= o) ? s[tid - o] : 0;
        __syncthreads();
        s[tid] += v;
        __syncthreads();
    }
    if (tid < SCAN_BLOCKS) g_bscan[tid] = s[tid] - val;
}
__global__ void scan_c_kernel() {
    int t = blockIdx.x * 256 + threadIdx.x;
    if (t >= N_NODES) return;
    int o = g_off[t] + g_bscan[t >> 8];
    g_off[t] = o;
    g_pos[t] = o;
}

// ---------------------------------------------------------------------------
// counting sort: bucket src ids by dst
// ---------------------------------------------------------------------------
__global__ void sort_kernel(const int* __restrict__ ei) {
    int e = blockIdx.x * 256 + threadIdx.x;
    if (e >= N_EDGES) return;
    int dst = ei[N_EDGES + e];
    int p = atomicAdd(&g_pos[dst], 1);
    g_srcs[p] = ei[e];
}

// ---------------------------------------------------------------------------
// tensor-core GEMM (mma.sync fp16), K=768  — verified structure + ybase chunk
// 128x128 tile, BK=64, 8 warps (4M x 2N), 3-stage cp.async
// blockIdx.x: 0,1 -> y_l (fp16 out), 2,3 -> y_r (fp32 out)
// ---------------------------------------------------------------------------
#define STAGE_BYTES 36864
#define SMEM_BYTES  (3 * STAGE_BYTES)

__global__ void __launch_bounds__(256, 2) gemm_tc_kernel(int ybase) {
    extern __shared__ char smem[];
    const uint32_t sb  = smem_u32(smem);
    const int tid  = threadIdx.x;
    const int lane = tid & 31;
    const int wid  = tid >> 5;
    const int wm   = wid & 3;
    const int wn   = wid >> 2;
    const int nb    = blockIdx.x * 128;
    const int mbase = (ybase + blockIdx.y) * 128;

    auto issue = [&](int s, int buf) {
        const int kb = s * 64;
        const uint32_t abase = sb + buf * STAGE_BYTES;
        const uint32_t bbase = abase + 18432;
#pragma unroll
        for (int j = 0; j < 4; j++) {
            int id  = tid + j * 256;
            int row = id >> 3, c = id & 7;
            cp16(abase + row * 144 + c * 16, g_A + (size_t)(mbase + row) * D_IN + kb + c * 8);
            cp16(bbase + row * 144 + c * 16, g_B + (size_t)(nb  + row) * D_IN + kb + c * 8);
        }
        cp_commit();
    };

    float d[2][8][4];
#pragma unroll
    for (int mt = 0; mt < 2; mt++)
#pragma unroll
        for (int nt = 0; nt < 8; nt++)
#pragma unroll
            for (int q = 0; q < 4; q++) d[mt][nt][q] = 0.f;

    issue(0, 0);
    issue(1, 1);

    const int arow = lane & 15, ahalf = lane >> 4;
    const int brow = (lane & 7) + ((lane >> 4) & 1) * 8, bhalf = (lane >> 3) & 1;

    for (int s = 0; s < KSTEPS; s++) {
        if (s == KSTEPS - 1) cp_wait<0>(); else cp_wait<1>();
        __syncthreads();
        if (s + 2 < KSTEPS) issue(s + 2, (s + 2) % 3);

        const int buf = s % 3;
        const uint32_t abase = sb + buf * STAGE_BYTES + (wm * 32) * 144;
        const uint32_t bbase = sb + buf * STAGE_BYTES + 18432 + (wn * 64) * 144;

#pragma unroll
        for (int kk = 0; kk < 4; kk++) {
            uint32_t ar[2][4];
#pragma unroll
            for (int mt = 0; mt < 2; mt++)
                ldm_x4(ar[mt], abase + (mt * 16 + arow) * 144 + kk * 32 + ahalf * 16);
            uint32_t br[4][4];
#pragma unroll
            for (int bt = 0; bt < 4; bt++)
                ldm_x4(br[bt], bbase + (bt * 16 + brow) * 144 + kk * 32 + bhalf * 16);
#pragma unroll
            for (int mt = 0; mt < 2; mt++)
#pragma unroll
                for (int nt = 0; nt < 8; nt++)
                    mma16816(d[mt][nt], ar[mt], br[nt >> 1][(nt & 1) * 2],
                             br[nt >> 1][(nt & 1) * 2 + 1]);
        }
    }

    const bool is_l = (blockIdx.x < 2);
#pragma unroll
    for (int mt = 0; mt < 2; mt++) {
        int row = mbase + wm * 32 + mt * 16 + (lane >> 2);
#pragma unroll
        for (int nt = 0; nt < 8; nt++) {
            int col = nb + wn * 64 + nt * 8 + (lane & 3) * 2;
            if (is_l) {
                __half2 p0 = __floats2half2_rn(d[mt][nt][0], d[mt][nt][1]);
                __half2 p1 = __floats2half2_rn(d[mt][nt][2], d[mt][nt][3]);
                if (row < N_NODES)
                    *reinterpret_cast<__half2*>(g_yl + (size_t)row * 256 + col) = p0;
                if (row + 8 < N_NODES)
                    *reinterpret_cast<__half2*>(g_yl + (size_t)(row + 8) * 256 + col) = p1;
            } else {
                int c2 = col - 256;
                if (row < N_NODES)
                    *reinterpret_cast<float2*>(g_yr + (size_t)row * 256 + c2) =
                        make_float2(d[mt][nt][0], d[mt][nt][1]);
                if (row + 8 < N_NODES)
                    *reinterpret_cast<float2*>(g_yr + (size_t)(row + 8) * 256 + c2) =
                        make_float2(d[mt][nt][2], d[mt][nt][3]);
            }
        }
    }
}

// ---------------------------------------------------------------------------
// fused aggregation + hidden + layer-2 projection (warp per node, MLP=2)
// ---------------------------------------------------------------------------
#define AGG_BLOCKS 296
#define AGG_WARPS  (AGG_BLOCKS * 8)
#define NODES_PER_WARP ((N_NODES + AGG_WARPS - 1) / AGG_WARPS)   // 22

__global__ void __launch_bounds__(256) agg_fused_kernel(
    const float* __restrict__ b1,
    const float* __restrict__ W2l, const float* __restrict__ W2r)
{
    int tid = threadIdx.x, lane = tid & 31;
    int gwarp = blockIdx.x * 8 + (tid >> 5);
    int node0 = gwarp * NODES_PER_WARP;
    if (node0 >= N_NODES) return;
    int node1 = min(node0 + NODES_PER_WARP, N_NODES);

    float wr[4][8], b1r[8];
    {
        const float* base = b1 + lane * 8;
        *reinterpret_cast<float4*>(&b1r[0]) = *reinterpret_cast<const float4*>(base);
        *reinterpret_cast<float4*>(&b1r[4]) = *reinterpret_cast<const float4*>(base + 4);
#pragma unroll
        for (int k = 0; k < 2; k++) {
            const float* wl  = W2l + k * 256 + lane * 8;
            const float* wrp = W2r + k * 256 + lane * 8;
            *reinterpret_cast<float4*>(&wr[k][0])     = *reinterpret_cast<const float4*>(wl);
            *reinterpret_cast<float4*>(&wr[k][4])     = *reinterpret_cast<const float4*>(wl + 4);
            *reinterpret_cast<float4*>(&wr[k + 2][0]) = *reinterpret_cast<const float4*>(wrp);
            *reinterpret_cast<float4*>(&wr[k + 2][4]) = *reinterpret_cast<const float4*>(wrp + 4);
        }
    }

    for (int node = node0; node < node1; node++) {
        int off = g_off[node], deg = g_deg[node];
        float acc[8];
#pragma unroll
        for (int j = 0; j < 8; j++) acc[j] = 0.f;

        int e = 0;
        for (; e + 2 <= deg; e += 2) {
            int s0 = g_srcs[off + e];
            int s1 = g_srcs[off + e + 1];
            uint4 v0 = *reinterpret_cast<const uint4*>(g_yl + (size_t)s0 * 256 + lane * 8);
            uint4 v1 = *reinterpret_cast<const uint4*>(g_yl + (size_t)s1 * 256 + lane * 8);
            const __half2* h0 = reinterpret_cast<const __half2*>(&v0);
            const __half2* h1 = reinterpret_cast<const __half2*>(&v1);
#pragma unroll
            for (int q = 0; q < 4; q++) {
                float2 f0 = __half22float2(h0[q]);
                float2 f1 = __half22float2(h1[q]);
                acc[q * 2]     += f0.x + f1.x;
                acc[q * 2 + 1] += f0.y + f1.y;
            }
        }
        if (e < deg) {
            int s0 = g_srcs[off + e];
            uint4 v0 = *reinterpret_cast<const uint4*>(g_yl + (size_t)s0 * 256 + lane * 8);
            const __half2* h0 = reinterpret_cast<const __half2*>(&v0);
#pragma unroll
            for (int q = 0; q < 4; q++) {
                float2 f0 = __half22float2(h0[q]);
                acc[q * 2]     += f0.x;
                acc[q * 2 + 1] += f0.y;
            }
        }

        float inv = 1.0f / fmaxf((float)deg, 1.0f);
        const float* yrp = g_yr + (size_t)node * 256 + lane * 8;
        float4 y0 = *reinterpret_cast<const float4*>(yrp);
        float4 y1 = *reinterpret_cast<const float4*>(yrp + 4);
        float yv[8] = {y0.x, y0.y, y0.z, y0.w, y1.x, y1.y, y1.z, y1.w};

        float a0 = 0.f, a1 = 0.f, a2 = 0.f, a3 = 0.f;
#pragma unroll
        for (int j = 0; j < 8; j++) {
            float h = fmaxf(fmaf(acc[j], inv, yv[j] + b1r[j]), 0.f);
            a0 = fmaf(h, wr[0][j], a0);
            a1 = fmaf(h, wr[1][j], a1);
            a2 = fmaf(h, wr[2][j], a2);
            a3 = fmaf(h, wr[3][j], a3);
        }
#pragma unroll
        for (int s = 16; s > 0; s >>= 1) {
            a0 += __shfl_xor_sync(0xFFFFFFFFu, a0, s);
            a1 += __shfl_xor_sync(0xFFFFFFFFu, a1, s);
            a2 += __shfl_xor_sync(0xFFFFFFFFu, a2, s);
            a3 += __shfl_xor_sync(0xFFFFFFFFu, a3, s);
        }
        if (lane == 0)
            *reinterpret_cast<float4*>(g_z + (size_t)node * 4) = make_float4(a0, a1, a2, a3);
    }
}

// ---------------------------------------------------------------------------
// fused layer-2 aggregation + output (thread per node, MLP=2)
// ---------------------------------------------------------------------------
__global__ void final_kernel(const float* __restrict__ b2, float* __restrict__ out) {
    int i = blockIdx.x * 256 + threadIdx.x;
    if (i >= N_NODES) return;
    int off = g_off[i], deg = g_deg[i];
    float s0 = 0.f, s1 = 0.f;
    int e = 0;
    for (; e + 2 <= deg; e += 2) {
        int a = g_srcs[off + e], b = g_srcs[off + e + 1];
        float2 za = *reinterpret_cast<const float2*>(g_z + (size_t)a * 4);
        float2 zb = *reinterpret_cast<const float2*>(g_z + (size_t)b * 4);
        s0 += za.x + zb.x; s1 += za.y + zb.y;
    }
    if (e < deg) {
        int a = g_srcs[off + e];
        float2 za = *reinterpret_cast<const float2*>(g_z + (size_t)a * 4);
        s0 += za.x; s1 += za.y;
    }
    float inv = 1.0f / fmaxf((float)deg, 1.0f);
    float2 zr = *reinterpret_cast<const float2*>(g_z + (size_t)i * 4 + 2);
    out[(size_t)i * 2 + 0] = fmaf(s0, inv, zr.x + b2[0]);
    out[(size_t)i * 2 + 1] = fmaf(s1, inv, zr.y + b2[1]);
}

extern "C" void kernel_launch(void* const* d_in, const int* in_sizes, int n_in,
                              void* d_out, int out_size) {
    const float* x    = (const float*)d_in[0];
    const int*   ei   = (const int*)d_in[1];
    const float* W1l  = (const float*)d_in[2];
    const float* b1   = (const float*)d_in[3];
    const float* W1r  = (const float*)d_in[4];
    const float* W2l  = (const float*)d_in[5];
    const float* b2   = (const float*)d_in[6];
    const float* W2r  = (const float*)d_in[7];
    float*       out  = (float*)d_out;

    static bool init_done = false;
    static cudaStream_t s2, s3;
    static cudaEvent_t  evFork, evB, evJoin, evG, evX[NCHUNK];
    if (!init_done) {
        cudaFuncSetAttribute(gemm_tc_kernel,
                             cudaFuncAttributeMaxDynamicSharedMemorySize, SMEM_BYTES);
        cudaStreamCreateWithFlags(&s2, cudaStreamNonBlocking);
        cudaStreamCreateWithFlags(&s3, cudaStreamNonBlocking);
        cudaEventCreateWithFlags(&evFork, cudaEventDisableTiming);
        cudaEventCreateWithFlags(&evB,    cudaEventDisableTiming);
        cudaEventCreateWithFlags(&evJoin, cudaEventDisableTiming);
        cudaEventCreateWithFlags(&evG,    cudaEventDisableTiming);
        for (int k = 0; k < NCHUNK; k++)
            cudaEventCreateWithFlags(&evX[k], cudaEventDisableTiming);
        init_done = true;
    }

    // y-stripe chunking: 391 stripes -> 98,98,98,97
    const int ys[NCHUNK]    = {98, 98, 98, 97};
    const int ybase[NCHUNK] = {0, 98, 196, 294};

    cudaEventRecord(evFork, 0);
    cudaStreamWaitEvent(s2, evFork, 0);
    cudaStreamWaitEvent(s3, evFork, 0);

    // s2: W conversion + CSR build
    zero_deg_kernel<<<SCAN_BLOCKS, 256, 0, s2>>>();
    conv_w_kernel<<<(512 * D_IN + 255) / 256, 256, 0, s2>>>(W1l, W1r, ei);
    cudaEventRecord(evB, s2);                       // g_B ready
    scan_a_kernel<<<SCAN_BLOCKS, 256, 0, s2>>>();
    scan_b_kernel<<<1, 256, 0, s2>>>();
    scan_c_kernel<<<SCAN_BLOCKS, 256, 0, s2>>>();
    sort_kernel<<<(N_EDGES + 255) / 256, 256, 0, s2>>>(ei);
    cudaEventRecord(evJoin, s2);                    // CSR ready

    // stream 0: conv_x chunks; s3: GEMM chunks pipelined behind them
    cudaStreamWaitEvent(s3, evB, 0);
    for (int k = 0; k < NCHUNK; k++) {
        int m0 = ybase[k] * 128;
        int m1 = (k == NCHUNK - 1) ? N_NODES : (ybase[k] + ys[k]) * 128;
        int nthreads = (m1 - m0) * (D_IN / 4);
        conv_x_kernel<<<(nthreads + 255) / 256, 256>>>(x, m0, m1);
        cudaEventRecord(evX[k], 0);
        cudaStreamWaitEvent(s3, evX[k], 0);
        dim3 gg(4, ys[k]);
        gemm_tc_kernel<<<gg, 256, SMEM_BYTES, s3>>>(ybase[k]);
    }
    cudaEventRecord(evG, s3);

    // join: aggregation needs GEMM output + CSR
    cudaStreamWaitEvent(0, evG, 0);
    cudaStreamWaitEvent(0, evJoin, 0);
    agg_fused_kernel<<<AGG_BLOCKS, 256>>>(b1, W2l, W2r);
    final_kernel<<<(N_NODES + 255) / 256, 256>>>(b2, out);
}

// round 17
// speedup vs baseline: 1.0849x; 1.0849x over previous
#include <cuda_runtime.h>
#include <cuda_fp16.h>
#include <cstdint>

#define N_NODES 50000
#define N_EDGES 250000
#define D_IN    768
#define D_HID   256

#define M_PAD   50048           // 391 * 128
#define KSTEPS  12              // 768 / 64
#define SCAN_BLOCKS 196         // ceil(50000/256)

__device__ __half g_yl[(size_t)N_NODES * 256];    // y_l = x@W1_l^T  (fp16)
__device__ __half g_yr16[(size_t)N_NODES * 256];  // y_r = x@W1_r^T  (fp16)
__device__ float  g_z[(size_t)N_NODES * 4];       // zl0,zl1,zr0,zr1
__device__ __half g_A[(size_t)M_PAD * D_IN];      // x fp16; padded rows stay 0
__device__ __half g_B[(size_t)512 * D_IN];        // rows 0..255 = W1_l, 256..511 = W1_r
__device__ int    g_deg[N_NODES];
__device__ int    g_off[N_NODES];
__device__ int    g_pos[N_NODES];
__device__ int    g_srcs[N_EDGES];
__device__ int    g_bsum[SCAN_BLOCKS];
__device__ int    g_bscan[SCAN_BLOCKS];

// ---------------------------------------------------------------------------
// helpers
// ---------------------------------------------------------------------------
__device__ __forceinline__ uint32_t smem_u32(const void* p) {
    uint32_t a;
    asm("{ .reg .u64 t; cvta.to.shared.u64 t, %1; cvt.u32.u64 %0, t; }" : "=r"(a) : "l"(p));
    return a;
}
__device__ __forceinline__ void cp16(uint32_t dst, const void* src) {
    asm volatile("cp.async.cg.shared.global [%0], [%1], 16;" :: "r"(dst), "l"(src));
}
__device__ __forceinline__ void cp_commit() { asm volatile("cp.async.commit_group;" ::: "memory"); }
template <int N> __device__ __forceinline__ void cp_wait() {
    asm volatile("cp.async.wait_group %0;" :: "n"(N) : "memory");
}
__device__ __forceinline__ void ldm_x4(uint32_t* r, uint32_t addr) {
    asm volatile("ldmatrix.sync.aligned.m8n8.x4.shared.b16 {%0,%1,%2,%3}, [%4];"
                 : "=r"(r[0]), "=r"(r[1]), "=r"(r[2]), "=r"(r[3]) : "r"(addr));
}
__device__ __forceinline__ void mma16816(float* d, const uint32_t* a, uint32_t b0, uint32_t b1) {
    asm volatile(
        "mma.sync.aligned.m16n8k16.row.col.f32.f16.f16.f32 "
        "{%0,%1,%2,%3}, {%4,%5,%6,%7}, {%8,%9}, {%0,%1,%2,%3};"
        : "+f"(d[0]), "+f"(d[1]), "+f"(d[2]), "+f"(d[3])
        : "r"(a[0]), "r"(a[1]), "r"(a[2]), "r"(a[3]), "r"(b0), "r"(b1));
}

// ---------------------------------------------------------------------------
// zero degree histogram (side stream, before conv_w's atomics)
// ---------------------------------------------------------------------------
__global__ void zero_deg_kernel() {
    int t = blockIdx.x * 256 + threadIdx.x;
    if (t < N_NODES) g_deg[t] = 0;
}

// ---------------------------------------------------------------------------
// convert x -> fp16 (main stream)
// ---------------------------------------------------------------------------
__global__ void conv_x_kernel(const float* __restrict__ x) {
    int t = blockIdx.x * 256 + threadIdx.x;
    if (t >= N_NODES * (D_IN / 4)) return;
    int m = t / (D_IN / 4), c4 = t % (D_IN / 4);
    float4 v = *reinterpret_cast<const float4*>(x + (size_t)m * D_IN + c4 * 4);
    __half2 h0 = __floats2half2_rn(v.x, v.y);
    __half2 h1 = __floats2half2_rn(v.z, v.w);
    *reinterpret_cast<uint2*>(g_A + (size_t)m * D_IN + c4 * 4) =
        make_uint2(*reinterpret_cast<uint32_t*>(&h0), *reinterpret_cast<uint32_t*>(&h1));
}

// ---------------------------------------------------------------------------
// convert W1 -> fp16; also histogram dst degrees (after zero_deg on s2)
// ---------------------------------------------------------------------------
__global__ void conv_w_kernel(const float* __restrict__ Wl, const float* __restrict__ Wr,
                              const int* __restrict__ ei) {
    int t = blockIdx.x * 256 + threadIdx.x;
    if (t < N_EDGES) atomicAdd(&g_deg[ei[N_EDGES + t]], 1);
    if (t >= 512 * D_IN) return;
    int r = t / D_IN, c = t % D_IN;
    float v = (r < 256) ? Wl[(size_t)r * D_IN + c] : Wr[(size_t)(r - 256) * D_IN + c];
    g_B[(size_t)r * D_IN + c] = __float2half_rn(v);
}

// ---------------------------------------------------------------------------
// exclusive scan of g_deg -> g_off (3 passes)
// ---------------------------------------------------------------------------
__global__ void scan_a_kernel() {
    __shared__ int s[256];
    int tid = threadIdx.x, t = blockIdx.x * 256 + tid;
    int val = (t < N_NODES) ? g_deg[t] : 0;
    s[tid] = val; __syncthreads();
#pragma unroll
    for (int o = 1; o < 256; o <<= 1) {
        int v = (tid >= o) ? s[tid - o] : 0;
        __syncthreads();
        s[tid] += v;
        __syncthreads();
    }
    if (t < N_NODES) g_off[t] = s[tid] - val;
    if (tid == 255) g_bsum[blockIdx.x] = s[255];
}
__global__ void scan_b_kernel() {
    __shared__ int s[256];
    int tid = threadIdx.x;
    int val = (tid < SCAN_BLOCKS) ? g_bsum[tid] : 0;
    s[tid] = val; __syncthreads();
#pragma unroll
    for (int o = 1; o < 256; o <<= 1) {
        int v = (tid >= o) ? s[tid - o] : 0;
        __syncthreads();
        s[tid] += v;
        __syncthreads();
    }
    if (tid < SCAN_BLOCKS) g_bscan[tid] = s[tid] - val;
}
__global__ void scan_c_kernel() {
    int t = blockIdx.x * 256 + threadIdx.x;
    if (t >= N_NODES) return;
    int o = g_off[t] + g_bscan[t >> 8];
    g_off[t] = o;
    g_pos[t] = o;
}

// ---------------------------------------------------------------------------
// counting sort: bucket src ids by dst
// ---------------------------------------------------------------------------
__global__ void sort_kernel(const int* __restrict__ ei) {
    int e = blockIdx.x * 256 + threadIdx.x;
    if (e >= N_EDGES) return;
    int dst = ei[N_EDGES + e];
    int p = atomicAdd(&g_pos[dst], 1);
    g_srcs[p] = ei[e];
}

// ---------------------------------------------------------------------------
// tensor-core GEMM (mma.sync fp16), K=768  — verified structure
// 128x128 tile, BK=64, 8 warps (4M x 2N), 3-stage cp.async
// blockIdx.x: 0,1 -> y_l (fp16 out), 2,3 -> y_r (fp16 out)
// ---------------------------------------------------------------------------
#define STAGE_BYTES 36864
#define SMEM_BYTES  (3 * STAGE_BYTES)

__global__ void __launch_bounds__(256, 2) gemm_tc_kernel() {
    extern __shared__ char smem[];
    const uint32_t sb  = smem_u32(smem);
    const int tid  = threadIdx.x;
    const int lane = tid & 31;
    const int wid  = tid >> 5;
    const int wm   = wid & 3;
    const int wn   = wid >> 2;
    const int nb    = blockIdx.x * 128;
    const int mbase = blockIdx.y * 128;

    auto issue = [&](int s, int buf) {
        const int kb = s * 64;
        const uint32_t abase = sb + buf * STAGE_BYTES;
        const uint32_t bbase = abase + 18432;
#pragma unroll
        for (int j = 0; j < 4; j++) {
            int id  = tid + j * 256;
            int row = id >> 3, c = id & 7;
            cp16(abase + row * 144 + c * 16, g_A + (size_t)(mbase + row) * D_IN + kb + c * 8);
            cp16(bbase + row * 144 + c * 16, g_B + (size_t)(nb  + row) * D_IN + kb + c * 8);
        }
        cp_commit();
    };

    float d[2][8][4];
#pragma unroll
    for (int mt = 0; mt < 2; mt++)
#pragma unroll
        for (int nt = 0; nt < 8; nt++)
#pragma unroll
            for (int q = 0; q < 4; q++) d[mt][nt][q] = 0.f;

    issue(0, 0);
    issue(1, 1);

    const int arow = lane & 15, ahalf = lane >> 4;
    const int brow = (lane & 7) + ((lane >> 4) & 1) * 8, bhalf = (lane >> 3) & 1;

    for (int s = 0; s < KSTEPS; s++) {
        if (s == KSTEPS - 1) cp_wait<0>(); else cp_wait<1>();
        __syncthreads();
        if (s + 2 < KSTEPS) issue(s + 2, (s + 2) % 3);

        const int buf = s % 3;
        const uint32_t abase = sb + buf * STAGE_BYTES + (wm * 32) * 144;
        const uint32_t bbase = sb + buf * STAGE_BYTES + 18432 + (wn * 64) * 144;

#pragma unroll
        for (int kk = 0; kk < 4; kk++) {
            uint32_t ar[2][4];
#pragma unroll
            for (int mt = 0; mt < 2; mt++)
                ldm_x4(ar[mt], abase + (mt * 16 + arow) * 144 + kk * 32 + ahalf * 16);
            uint32_t br[4][4];
#pragma unroll
            for (int bt = 0; bt < 4; bt++)
                ldm_x4(br[bt], bbase + (bt * 16 + brow) * 144 + kk * 32 + bhalf * 16);
#pragma unroll
            for (int mt = 0; mt < 2; mt++)
#pragma unroll
                for (int nt = 0; nt < 8; nt++)
                    mma16816(d[mt][nt], ar[mt], br[nt >> 1][(nt & 1) * 2],
                             br[nt >> 1][(nt & 1) * 2 + 1]);
        }
    }

    const bool is_l = (blockIdx.x < 2);
#pragma unroll
    for (int mt = 0; mt < 2; mt++) {
        int row = mbase + wm * 32 + mt * 16 + (lane >> 2);
#pragma unroll
        for (int nt = 0; nt < 8; nt++) {
            int col = nb + wn * 64 + nt * 8 + (lane & 3) * 2;
            __half2 p0 = __floats2half2_rn(d[mt][nt][0], d[mt][nt][1]);
            __half2 p1 = __floats2half2_rn(d[mt][nt][2], d[mt][nt][3]);
            if (is_l) {
                if (row < N_NODES)
                    *reinterpret_cast<__half2*>(g_yl + (size_t)row * 256 + col) = p0;
                if (row + 8 < N_NODES)
                    *reinterpret_cast<__half2*>(g_yl + (size_t)(row + 8) * 256 + col) = p1;
            } else {
                int c2 = col - 256;
                if (row < N_NODES)
                    *reinterpret_cast<__half2*>(g_yr16 + (size_t)row * 256 + c2) = p0;
                if (row + 8 < N_NODES)
                    *reinterpret_cast<__half2*>(g_yr16 + (size_t)(row + 8) * 256 + c2) = p1;
            }
        }
    }
}

// ---------------------------------------------------------------------------
// fused aggregation + hidden + layer-2 projection (warp per node, MLP=2)
// ---------------------------------------------------------------------------
#define AGG_BLOCKS 296
#define AGG_WARPS  (AGG_BLOCKS * 8)
#define NODES_PER_WARP ((N_NODES + AGG_WARPS - 1) / AGG_WARPS)   // 22

__global__ void __launch_bounds__(256) agg_fused_kernel(
    const float* __restrict__ b1,
    const float* __restrict__ W2l, const float* __restrict__ W2r)
{
    int tid = threadIdx.x, lane = tid & 31;
    int gwarp = blockIdx.x * 8 + (tid >> 5);
    int node0 = gwarp * NODES_PER_WARP;
    if (node0 >= N_NODES) return;
    int node1 = min(node0 + NODES_PER_WARP, N_NODES);

    float wr[4][8], b1r[8];
    {
        const float* base = b1 + lane * 8;
        *reinterpret_cast<float4*>(&b1r[0]) = *reinterpret_cast<const float4*>(base);
        *reinterpret_cast<float4*>(&b1r[4]) = *reinterpret_cast<const float4*>(base + 4);
#pragma unroll
        for (int k = 0; k < 2; k++) {
            const float* wl  = W2l + k * 256 + lane * 8;
            const float* wrp = W2r + k * 256 + lane * 8;
            *reinterpret_cast<float4*>(&wr[k][0])     = *reinterpret_cast<const float4*>(wl);
            *reinterpret_cast<float4*>(&wr[k][4])     = *reinterpret_cast<const float4*>(wl + 4);
            *reinterpret_cast<float4*>(&wr[k + 2][0]) = *reinterpret_cast<const float4*>(wrp);
            *reinterpret_cast<float4*>(&wr[k + 2][4]) = *reinterpret_cast<const float4*>(wrp + 4);
        }
    }

    for (int node = node0; node < node1; node++) {
        int off = g_off[node], deg = g_deg[node];
        float acc[8];
#pragma unroll
        for (int j = 0; j < 8; j++) acc[j] = 0.f;

        int e = 0;
        for (; e + 2 <= deg; e += 2) {
            int s0 = g_srcs[off + e];
            int s1 = g_srcs[off + e + 1];
            uint4 v0 = *reinterpret_cast<const uint4*>(g_yl + (size_t)s0 * 256 + lane * 8);
            uint4 v1 = *reinterpret_cast<const uint4*>(g_yl + (size_t)s1 * 256 + lane * 8);
            const __half2* h0 = reinterpret_cast<const __half2*>(&v0);
            const __half2* h1 = reinterpret_cast<const __half2*>(&v1);
#pragma unroll
            for (int q = 0; q < 4; q++) {
                float2 f0 = __half22float2(h0[q]);
                float2 f1 = __half22float2(h1[q]);
                acc[q * 2]     += f0.x + f1.x;
                acc[q * 2 + 1] += f0.y + f1.y;
            }
        }
        if (e < deg) {
            int s0 = g_srcs[off + e];
            uint4 v0 = *reinterpret_cast<const uint4*>(g_yl + (size_t)s0 * 256 + lane * 8);
            const __half2* h0 = reinterpret_cast<const __half2*>(&v0);
#pragma unroll
            for (int q = 0; q < 4; q++) {
                float2 f0 = __half22float2(h0[q]);
                acc[q * 2]     += f0.x;
                acc[q * 2 + 1] += f0.y;
            }
        }

        float inv = 1.0f / fmaxf((float)deg, 1.0f);
        float yv[8];
        {
            uint4 vr = *reinterpret_cast<const uint4*>(g_yr16 + (size_t)node * 256 + lane * 8);
            const __half2* hr = reinterpret_cast<const __half2*>(&vr);
#pragma unroll
            for (int q = 0; q < 4; q++) {
                float2 f = __half22float2(hr[q]);
                yv[q * 2]     = f.x;
                yv[q * 2 + 1] = f.y;
            }
        }

        float a0 = 0.f, a1 = 0.f, a2 = 0.f, a3 = 0.f;
#pragma unroll
        for (int j = 0; j < 8; j++) {
            float h = fmaxf(fmaf(acc[j], inv, yv[j] + b1r[j]), 0.f);
            a0 = fmaf(h, wr[0][j], a0);
            a1 = fmaf(h, wr[1][j], a1);
            a2 = fmaf(h, wr[2][j], a2);
            a3 = fmaf(h, wr[3][j], a3);
        }
#pragma unroll
        for (int s = 16; s > 0; s >>= 1) {
            a0 += __shfl_xor_sync(0xFFFFFFFFu, a0, s);
            a1 += __shfl_xor_sync(0xFFFFFFFFu, a1, s);
            a2 += __shfl_xor_sync(0xFFFFFFFFu, a2, s);
            a3 += __shfl_xor_sync(0xFFFFFFFFu, a3, s);
        }
        if (lane == 0)
            *reinterpret_cast<float4*>(g_z + (size_t)node * 4) = make_float4(a0, a1, a2, a3);
    }
}

// ---------------------------------------------------------------------------
// fused layer-2 aggregation + output (thread per node, MLP=2)
// ---------------------------------------------------------------------------
__global__ void final_kernel(const float* __restrict__ b2, float* __restrict__ out) {
    int i = blockIdx.x * 256 + threadIdx.x;
    if (i >= N_NODES) return;
    int off = g_off[i], deg = g_deg[i];
    float s0 = 0.f, s1 = 0.f;
    int e = 0;
    for (; e + 2 <= deg; e += 2) {
        int a = g_srcs[off + e], b = g_srcs[off + e + 1];
        float2 za = *reinterpret_cast<const float2*>(g_z + (size_t)a * 4);
        float2 zb = *reinterpret_cast<const float2*>(g_z + (size_t)b * 4);
        s0 += za.x + zb.x; s1 += za.y + zb.y;
    }
    if (e < deg) {
        int a = g_srcs[off + e];
        float2 za = *reinterpret_cast<const float2*>(g_z + (size_t)a * 4);
        s0 += za.x; s1 += za.y;
    }
    float inv = 1.0f / fmaxf((float)deg, 1.0f);
    float2 zr = *reinterpret_cast<const float2*>(g_z + (size_t)i * 4 + 2);
    out[(size_t)i * 2 + 0] = fmaf(s0, inv, zr.x + b2[0]);
    out[(size_t)i * 2 + 1] = fmaf(s1, inv, zr.y + b2[1]);
}

extern "C" void kernel_launch(void* const* d_in, const int* in_sizes, int n_in,
                              void* d_out, int out_size) {
    const float* x    = (const float*)d_in[0];
    const int*   ei   = (const int*)d_in[1];
    const float* W1l  = (const float*)d_in[2];
    const float* b1   = (const float*)d_in[3];
    const float* W1r  = (const float*)d_in[4];
    const float* W2l  = (const float*)d_in[5];
    const float* b2   = (const float*)d_in[6];
    const float* W2r  = (const float*)d_in[7];
    float*       out  = (float*)d_out;

    static bool init_done = false;
    static cudaStream_t s2;
    static cudaEvent_t  evFork, evB, evJoin;
    if (!init_done) {
        cudaFuncSetAttribute(gemm_tc_kernel,
                             cudaFuncAttributeMaxDynamicSharedMemorySize, SMEM_BYTES);
        cudaStreamCreateWithFlags(&s2, cudaStreamNonBlocking);
        cudaEventCreateWithFlags(&evFork, cudaEventDisableTiming);
        cudaEventCreateWithFlags(&evB,    cudaEventDisableTiming);
        cudaEventCreateWithFlags(&evJoin, cudaEventDisableTiming);
        init_done = true;
    }

    // fork at the very start: s2 handles W conversion + full CSR build,
    // main stream handles x conversion + GEMM.
    cudaEventRecord(evFork, 0);
    cudaStreamWaitEvent(s2, evFork, 0);

    zero_deg_kernel<<<SCAN_BLOCKS, 256, 0, s2>>>();
    conv_w_kernel<<<(512 * D_IN + 255) / 256, 256, 0, s2>>>(W1l, W1r, ei);
    cudaEventRecord(evB, s2);                       // g_B ready
    scan_a_kernel<<<SCAN_BLOCKS, 256, 0, s2>>>();
    scan_b_kernel<<<1, 256, 0, s2>>>();
    scan_c_kernel<<<SCAN_BLOCKS, 256, 0, s2>>>();
    sort_kernel<<<(N_EDGES + 255) / 256, 256, 0, s2>>>(ei);
    cudaEventRecord(evJoin, s2);                    // CSR ready

    conv_x_kernel<<<(N_NODES * (D_IN / 4) + 255) / 256, 256>>>(x);

    cudaStreamWaitEvent(0, evB, 0);                 // GEMM needs g_B
    dim3 gg(4, M_PAD / 128);
    gemm_tc_kernel<<<gg, 256, SMEM_BYTES>>>();

    cudaStreamWaitEvent(0, evJoin, 0);              // agg needs the CSR
    agg_fused_kernel<<<AGG_BLOCKS, 256>>>(b1, W2l, W2r);
    final_kernel<<<(N_NODES + 255) / 256, 256>>>(b2, out);
}